// round 3
// baseline (speedup 1.0000x reference)
#include <cuda_runtime.h>
#include <math.h>

#define NN   50000
#define NE   800000
#define D    128
#define DOUT 40
#define NBLK ((NN + 255) / 256)   // 196

// scratch (allocation-free rule: __device__ globals)
__device__ float g_agg[NN * D];
__device__ float g_h1[NN * D];
__device__ float g_h2[NN * D];
__device__ float g_dinv[NN];
__device__ int   g_cnt[NN];
__device__ int   g_rowptr[NN];
__device__ int   g_cursor[NN];
__device__ int   g_bsum[256];
__device__ int   g_csr[NE];
__device__ int   g_is64;

// ---------------------------------------------------------------------------
// edge_index dtype detector: if data is int64 (values < 2^31), the high 32-bit
// word of each element is 0. For int32 data those words are random node ids.
__global__ void k_detect(const int* __restrict__ ei32) {
    int tid = threadIdx.x;
    int nz = 0;
    // inspect high words of would-be int64 elements 0..255
    for (int j = 0; j < 1; j++) {
        int v = ei32[2 * tid + 1];
        if (v != 0) nz = 1;
    }
    int cnt_nz = __syncthreads_count(nz);
    if (tid == 0) g_is64 = (cnt_nz == 0) ? 1 : 0;
}

__device__ __forceinline__ int edge_val(const void* ei, long long idx, int is64) {
    if (is64) return (int)((const long long*)ei)[idx];
    return ((const int*)ei)[idx];
}

// ---------------------------------------------------------------------------
__global__ void k_zero_cnt() {
    int i = blockIdx.x * blockDim.x + threadIdx.x;
    if (i < NN) g_cnt[i] = 0;
}

__global__ void __launch_bounds__(256) k_hist(const void* __restrict__ ei) {
    int e = blockIdx.x * blockDim.x + threadIdx.x;
    if (e >= NE) return;
    int is64 = g_is64;
    int d = edge_val(ei, (long long)NE + e, is64);
    atomicAdd(&g_cnt[d], 1);
}

// ---- 3-phase exclusive scan over g_cnt -> g_rowptr ----
__global__ void __launch_bounds__(256) k_scanA() {
    __shared__ int sb[256];
    int t = threadIdx.x;
    int i = blockIdx.x * 256 + t;
    int v = (i < NN) ? g_cnt[i] : 0;
    sb[t] = v;
    __syncthreads();
    for (int off = 1; off < 256; off <<= 1) {
        int tv = (t >= off) ? sb[t - off] : 0;
        __syncthreads();
        sb[t] += tv;
        __syncthreads();
    }
    int incl = sb[t];
    if (i < NN) g_rowptr[i] = incl - v;
    if (t == 255) g_bsum[blockIdx.x] = incl;
}

__global__ void __launch_bounds__(256) k_scanB() {
    __shared__ int sb[256];
    int t = threadIdx.x;
    int v = (t < NBLK) ? g_bsum[t] : 0;
    sb[t] = v;
    __syncthreads();
    for (int off = 1; off < 256; off <<= 1) {
        int tv = (t >= off) ? sb[t - off] : 0;
        __syncthreads();
        sb[t] += tv;
        __syncthreads();
    }
    if (t < NBLK) g_bsum[t] = sb[t] - v;   // exclusive block base
}

__global__ void __launch_bounds__(256) k_scanC() {
    int i = blockIdx.x * 256 + threadIdx.x;
    if (i < NN) {
        int rp = g_rowptr[i] + g_bsum[blockIdx.x];
        g_rowptr[i] = rp;
        g_cursor[i] = rp;
        g_dinv[i] = 1.0f / (float)max(g_cnt[i], 1);
    }
}

__global__ void __launch_bounds__(256) k_fill(const void* __restrict__ ei) {
    int e = blockIdx.x * blockDim.x + threadIdx.x;
    if (e >= NE) return;
    int is64 = g_is64;
    int s = edge_val(ei, e, is64);
    int d = edge_val(ei, (long long)NE + e, is64);
    int pos = atomicAdd(&g_cursor[d], 1);
    g_csr[pos] = s;
}

// ---------------------------------------------------------------------------
// gather-aggregate (mean): one warp per node, coalesced 512B row reads
__global__ void __launch_bounds__(256) k_agg(const float* __restrict__ feat_param,
                                             int use_h1) {
    int t = blockIdx.x * blockDim.x + threadIdx.x;
    int node = t >> 5;
    if (node >= NN) return;
    int lane = t & 31;
    const float* feat = use_h1 ? g_h1 : feat_param;

    int start = g_rowptr[node];
    int end = start + g_cnt[node];

    float4 acc0 = make_float4(0.f, 0.f, 0.f, 0.f);
    float4 acc1 = make_float4(0.f, 0.f, 0.f, 0.f);

    int e = start;
    for (; e + 1 < end; e += 2) {
        int s0 = g_csr[e];
        int s1 = g_csr[e + 1];
        float4 v0 = *((const float4*)(feat + (size_t)s0 * D) + lane);
        float4 v1 = *((const float4*)(feat + (size_t)s1 * D) + lane);
        acc0.x += v0.x; acc0.y += v0.y; acc0.z += v0.z; acc0.w += v0.w;
        acc1.x += v1.x; acc1.y += v1.y; acc1.z += v1.z; acc1.w += v1.w;
    }
    if (e < end) {
        int s0 = g_csr[e];
        float4 v0 = *((const float4*)(feat + (size_t)s0 * D) + lane);
        acc0.x += v0.x; acc0.y += v0.y; acc0.z += v0.z; acc0.w += v0.w;
    }

    float di = g_dinv[node];
    float4 r;
    r.x = (acc0.x + acc1.x) * di;
    r.y = (acc0.y + acc1.y) * di;
    r.z = (acc0.z + acc1.z) * di;
    r.w = (acc0.w + acc1.w) * di;
    *((float4*)(g_agg + (size_t)node * D) + lane) = r;
}

// ---------------------------------------------------------------------------
// fused SAGE layer: hout = relu([agg_mean | xin] @ [W_l;W_r]^T + b)
// block: 256 threads, 64 nodes x 128 outs; thread: 4 nodes x 8 outs; KC=32
#define KC   32
#define NT   64
#define PA   68     // sA row stride (nodes + 4)
#define PW   132    // sW row stride (outs + 4)

__global__ void __launch_bounds__(256) k_layer(const float* __restrict__ xin_param,
                                               const float* __restrict__ Wl,
                                               const float* __restrict__ Wr,
                                               const float* __restrict__ b,
                                               int first) {
    __shared__ __align__(16) float sA[KC * PA];   // A[k][node]  8704 B
    __shared__ __align__(16) float sW[KC * PW];   // W[k][out]  16896 B
    __shared__ float sb[128];

    const float* xin = first ? xin_param : g_h1;
    float* hout = first ? g_h1 : g_h2;

    int tid = threadIdx.x;
    int node0 = blockIdx.x * NT;
    if (tid < 128) sb[tid] = b[tid];

    int nx = tid & 15;   // node group
    int oy = tid >> 4;   // out group

    float acc[4][8];
#pragma unroll
    for (int i = 0; i < 4; i++)
#pragma unroll
        for (int j = 0; j < 8; j++) acc[i][j] = 0.f;

    int an = tid >> 2;            // 0..63 node for A-load
    int akq = (tid & 3) * 8;      // 0,8,16,24

    for (int kk = 0; kk < 256; kk += KC) {
        // A chunk: 64 nodes x 32 k
        {
            int node = node0 + an;
            const float* src = (kk < 128) ? (g_agg + (size_t)node * D + kk)
                                          : (xin + (size_t)node * D + (kk - 128));
            float4 v0 = make_float4(0.f, 0.f, 0.f, 0.f);
            float4 v1 = make_float4(0.f, 0.f, 0.f, 0.f);
            if (node < NN) {
                v0 = *(const float4*)(src + akq);
                v1 = *(const float4*)(src + akq + 4);
            }
            sA[(akq + 0) * PA + an] = v0.x;
            sA[(akq + 1) * PA + an] = v0.y;
            sA[(akq + 2) * PA + an] = v0.z;
            sA[(akq + 3) * PA + an] = v0.w;
            sA[(akq + 4) * PA + an] = v1.x;
            sA[(akq + 5) * PA + an] = v1.y;
            sA[(akq + 6) * PA + an] = v1.z;
            sA[(akq + 7) * PA + an] = v1.w;
        }
        // W chunk: 128 outs x 32 k  (coalesced global reads)
#pragma unroll
        for (int r = 0; r < 16; r++) {
            int i = r * 256 + tid;        // 0..4095
            int o = i >> 5;               // 0..127
            int kc = i & 31;
            int kg = kk + kc;
            float w = (kg < 128) ? Wl[o * 128 + kg] : Wr[o * 128 + (kg - 128)];
            sW[kc * PW + o] = w;
        }
        __syncthreads();
#pragma unroll
        for (int k = 0; k < KC; k++) {
            float4 a = *(const float4*)(sA + k * PA + nx * 4);
            float av[4] = {a.x, a.y, a.z, a.w};
#pragma unroll
            for (int j = 0; j < 8; j++) {
                float w = sW[k * PW + oy * 8 + j];
                acc[0][j] += av[0] * w;
                acc[1][j] += av[1] * w;
                acc[2][j] += av[2] * w;
                acc[3][j] += av[3] * w;
            }
        }
        __syncthreads();
    }

#pragma unroll
    for (int i = 0; i < 4; i++) {
        int node = node0 + nx * 4 + i;
        if (node < NN) {
#pragma unroll
            for (int j = 0; j < 8; j++) {
                int o = oy * 8 + j;
                float v = acc[i][j] + sb[o];
                hout[(size_t)node * D + o] = fmaxf(v, 0.f);
            }
        }
    }
}

// ---------------------------------------------------------------------------
// final: logits = [h1|h2] @ W_lin^T + b_lin ; log_softmax. 1 thread per node.
__global__ void __launch_bounds__(128) k_final(const float* __restrict__ Wlin,
                                               const float* __restrict__ blin,
                                               float* __restrict__ out) {
    __shared__ __align__(16) float sWt[256 * DOUT];   // [k][o]
    __shared__ float sb[DOUT];
    int tid = threadIdx.x;
    for (int i = tid; i < 256 * DOUT; i += 128) {
        int o = i >> 8;
        int k = i & 255;
        sWt[k * DOUT + o] = Wlin[o * 256 + k];
    }
    if (tid < DOUT) sb[tid] = blin[tid];
    __syncthreads();

    int node = blockIdx.x * 128 + tid;
    if (node >= NN) return;

    float acc[DOUT];
#pragma unroll
    for (int o = 0; o < DOUT; o++) acc[o] = sb[o];

    const float* h1p = g_h1 + (size_t)node * D;
    const float* h2p = g_h2 + (size_t)node * D;
#pragma unroll
    for (int half = 0; half < 2; half++) {
        const float* hp = half ? h2p : h1p;
        for (int k4 = 0; k4 < 128; k4 += 4) {
            float4 a = *(const float4*)(hp + k4);
            float av[4] = {a.x, a.y, a.z, a.w};
#pragma unroll
            for (int kkk = 0; kkk < 4; kkk++) {
                const float* wr = sWt + (half * 128 + k4 + kkk) * DOUT;
                float v = av[kkk];
#pragma unroll
                for (int o4 = 0; o4 < DOUT; o4 += 4) {
                    float4 w = *(const float4*)(wr + o4);
                    acc[o4 + 0] += v * w.x;
                    acc[o4 + 1] += v * w.y;
                    acc[o4 + 2] += v * w.z;
                    acc[o4 + 3] += v * w.w;
                }
            }
        }
    }

    float m = acc[0];
#pragma unroll
    for (int o = 1; o < DOUT; o++) m = fmaxf(m, acc[o]);
    float s = 0.f;
#pragma unroll
    for (int o = 0; o < DOUT; o++) s += expf(acc[o] - m);
    float lse = m + logf(s);
    float* op = out + (size_t)node * DOUT;
#pragma unroll
    for (int o = 0; o < DOUT; o++) op[o] = acc[o] - lse;
}

// ---------------------------------------------------------------------------
extern "C" void kernel_launch(void* const* d_in, const int* in_sizes, int n_in,
                              void* d_out, int out_size) {
    const float* x    = (const float*)d_in[0];
    const void*  ei   = d_in[1];
    const float* W1l  = (const float*)d_in[2];
    const float* b1   = (const float*)d_in[3];
    const float* W1r  = (const float*)d_in[4];
    const float* W2l  = (const float*)d_in[5];
    const float* b2   = (const float*)d_in[6];
    const float* W2r  = (const float*)d_in[7];
    const float* Wlin = (const float*)d_in[8];
    const float* blin = (const float*)d_in[9];
    float*       out  = (float*)d_out;

    const int edge_blocks  = (NE + 255) / 256;      // 3125
    const int agg_blocks   = (NN * 32 + 255) / 256; // 6250
    const int layer_blocks = (NN + NT - 1) / NT;    // 782
    const int final_blocks = (NN + 127) / 128;      // 391

    // CSR build (once, reused by both layers)
    k_detect<<<1, 256>>>((const int*)ei);
    k_zero_cnt<<<NBLK, 256>>>();
    k_hist<<<edge_blocks, 256>>>(ei);
    k_scanA<<<NBLK, 256>>>();
    k_scanB<<<1, 256>>>();
    k_scanC<<<NBLK, 256>>>();
    k_fill<<<edge_blocks, 256>>>(ei);

    // layer 1
    k_agg<<<agg_blocks, 256>>>(x, 0);
    k_layer<<<layer_blocks, 256>>>(x, W1l, W1r, b1, 1);

    // layer 2
    k_agg<<<agg_blocks, 256>>>(nullptr, 1);
    k_layer<<<layer_blocks, 256>>>(nullptr, W2l, W2r, b2, 0);

    // head
    k_final<<<final_blocks, 128>>>(Wlin, blin, out);
}

// round 5
// speedup vs baseline: 1.4413x; 1.4413x over previous
#include <cuda_runtime.h>
#include <cuda_bf16.h>
#include <math.h>
#include <stdint.h>

#define NN   50000
#define NE   800000
#define D    128
#define DOUT 40
#define NBLK ((NN + 255) / 256)   // 196

// scratch (allocation-free rule: __device__ globals)
__device__ float g_agg[NN * D];
__device__ float g_h1[NN * D];
__device__ float g_h2[NN * D];
__device__ float g_dinv[NN];
__device__ int   g_cnt[NN];
__device__ int   g_rowptr[NN];
__device__ int   g_cursor[NN];
__device__ int   g_bsum[256];
__device__ int   g_csr[NE];
__device__ int   g_is64;

// ---------------------------------------------------------------------------
// edge_index dtype detector
__global__ void k_detect(const int* __restrict__ ei32) {
    int tid = threadIdx.x;
    int nz = (ei32[2 * tid + 1] != 0) ? 1 : 0;
    int cnt_nz = __syncthreads_count(nz);
    if (tid == 0) g_is64 = (cnt_nz == 0) ? 1 : 0;
}

__device__ __forceinline__ int edge_val(const void* ei, long long idx, int is64) {
    if (is64) return (int)((const long long*)ei)[idx];
    return ((const int*)ei)[idx];
}

// ---------------------------------------------------------------------------
__global__ void k_zero_cnt() {
    int i = blockIdx.x * blockDim.x + threadIdx.x;
    if (i < NN) g_cnt[i] = 0;
}

__global__ void __launch_bounds__(256) k_hist(const void* __restrict__ ei) {
    int e = blockIdx.x * blockDim.x + threadIdx.x;
    if (e >= NE) return;
    int is64 = g_is64;
    int d = edge_val(ei, (long long)NE + e, is64);
    atomicAdd(&g_cnt[d], 1);
}

__global__ void __launch_bounds__(256) k_scanA() {
    __shared__ int sb[256];
    int t = threadIdx.x;
    int i = blockIdx.x * 256 + t;
    int v = (i < NN) ? g_cnt[i] : 0;
    sb[t] = v;
    __syncthreads();
    for (int off = 1; off < 256; off <<= 1) {
        int tv = (t >= off) ? sb[t - off] : 0;
        __syncthreads();
        sb[t] += tv;
        __syncthreads();
    }
    int incl = sb[t];
    if (i < NN) g_rowptr[i] = incl - v;
    if (t == 255) g_bsum[blockIdx.x] = incl;
}

__global__ void __launch_bounds__(256) k_scanB() {
    __shared__ int sb[256];
    int t = threadIdx.x;
    int v = (t < NBLK) ? g_bsum[t] : 0;
    sb[t] = v;
    __syncthreads();
    for (int off = 1; off < 256; off <<= 1) {
        int tv = (t >= off) ? sb[t - off] : 0;
        __syncthreads();
        sb[t] += tv;
        __syncthreads();
    }
    if (t < NBLK) g_bsum[t] = sb[t] - v;
}

__global__ void __launch_bounds__(256) k_scanC() {
    int i = blockIdx.x * 256 + threadIdx.x;
    if (i < NN) {
        int rp = g_rowptr[i] + g_bsum[blockIdx.x];
        g_rowptr[i] = rp;
        g_cursor[i] = rp;
        g_dinv[i] = 1.0f / (float)max(g_cnt[i], 1);
    }
}

__global__ void __launch_bounds__(256) k_fill(const void* __restrict__ ei) {
    int e = blockIdx.x * blockDim.x + threadIdx.x;
    if (e >= NE) return;
    int is64 = g_is64;
    int s = edge_val(ei, e, is64);
    int d = edge_val(ei, (long long)NE + e, is64);
    int pos = atomicAdd(&g_cursor[d], 1);
    g_csr[pos] = s;
}

// ---------------------------------------------------------------------------
// gather-aggregate (mean): one warp per node
__global__ void __launch_bounds__(256) k_agg(const float* __restrict__ feat_param,
                                             int use_h1) {
    int t = blockIdx.x * blockDim.x + threadIdx.x;
    int node = t >> 5;
    if (node >= NN) return;
    int lane = t & 31;
    const float* feat = use_h1 ? g_h1 : feat_param;

    int start = g_rowptr[node];
    int end = start + g_cnt[node];

    float4 acc0 = make_float4(0.f, 0.f, 0.f, 0.f);
    float4 acc1 = make_float4(0.f, 0.f, 0.f, 0.f);

    int e = start;
    for (; e + 1 < end; e += 2) {
        int s0 = g_csr[e];
        int s1 = g_csr[e + 1];
        float4 v0 = *((const float4*)(feat + (size_t)s0 * D) + lane);
        float4 v1 = *((const float4*)(feat + (size_t)s1 * D) + lane);
        acc0.x += v0.x; acc0.y += v0.y; acc0.z += v0.z; acc0.w += v0.w;
        acc1.x += v1.x; acc1.y += v1.y; acc1.z += v1.z; acc1.w += v1.w;
    }
    if (e < end) {
        int s0 = g_csr[e];
        float4 v0 = *((const float4*)(feat + (size_t)s0 * D) + lane);
        acc0.x += v0.x; acc0.y += v0.y; acc0.z += v0.z; acc0.w += v0.w;
    }

    float di = g_dinv[node];
    float4 r;
    r.x = (acc0.x + acc1.x) * di;
    r.y = (acc0.y + acc1.y) * di;
    r.z = (acc0.z + acc1.z) * di;
    r.w = (acc0.w + acc1.w) * di;
    *((float4*)(g_agg + (size_t)node * D) + lane) = r;
}

// ---------------------------------------------------------------------------
// mma.sync bf16 layer with hi/lo split (3 passes: hh + hl + lh).
// Per 128-node tile: D[128,128] = A[128,256] @ W[128,256]^T, fp32 accum.
#define TILES_PER_BLK 3
#define NTILES ((NN + 127) / 128)                              // 391
#define MMA_GRID ((NTILES + TILES_PER_BLK - 1) / TILES_PER_BLK) // 131

// smem byte offsets
#define SB_OFF   0
#define A_HI_OFF 1024
#define A_LO_OFF (A_HI_OFF + 34816)       // 128 rows * 272B
#define B_HI_OFF (A_LO_OFF + 34816)       // 70656
#define B_LO_OFF (B_HI_OFF + 67584)       // 128 rows * 528B
#define SMEM_MMA_BYTES (B_LO_OFF + 67584) // 205824
#define RSA 272   // A row stride bytes (136 bf16)
#define RSB 528   // B row stride bytes (264 bf16)

__device__ __forceinline__ uint32_t smem_u32(const void* p) {
    uint32_t a;
    asm("{ .reg .u64 t; cvta.to.shared.u64 t, %1; cvt.u32.u64 %0, t; }"
        : "=r"(a) : "l"(p));
    return a;
}

__device__ __forceinline__ void ldm_x4(uint32_t addr, uint32_t* r) {
    asm volatile("ldmatrix.sync.aligned.m8n8.x4.shared.b16 {%0,%1,%2,%3}, [%4];"
                 : "=r"(r[0]), "=r"(r[1]), "=r"(r[2]), "=r"(r[3]) : "r"(addr));
}

__device__ __forceinline__ void mma_bf16(float* d, const uint32_t* a,
                                         const uint32_t* b) {
    asm volatile(
        "mma.sync.aligned.m16n8k16.row.col.f32.bf16.bf16.f32 "
        "{%0,%1,%2,%3}, {%4,%5,%6,%7}, {%8,%9}, {%0,%1,%2,%3};"
        : "+f"(d[0]), "+f"(d[1]), "+f"(d[2]), "+f"(d[3])
        : "r"(a[0]), "r"(a[1]), "r"(a[2]), "r"(a[3]), "r"(b[0]), "r"(b[1]));
}

__device__ __forceinline__ void cvt_pair(float x0, float x1, uint32_t& hi,
                                         uint32_t& lo) {
    __nv_bfloat16 h0 = __float2bfloat16(x0);
    __nv_bfloat16 h1 = __float2bfloat16(x1);
    float r0 = x0 - __bfloat162float(h0);
    float r1 = x1 - __bfloat162float(h1);
    __nv_bfloat162 hp(h0, h1);
    __nv_bfloat162 lp(__float2bfloat16(r0), __float2bfloat16(r1));
    hi = *reinterpret_cast<uint32_t*>(&hp);
    lo = *reinterpret_cast<uint32_t*>(&lp);
}

__global__ void __launch_bounds__(256, 1) k_layer_mma(const float* __restrict__ xin_param,
                                                      const float* __restrict__ Wl,
                                                      const float* __restrict__ Wr,
                                                      const float* __restrict__ b,
                                                      int first) {
    extern __shared__ char smem[];
    uint32_t sbase = smem_u32(smem);
    float* sbias = (float*)(smem + SB_OFF);

    const float* xin = first ? xin_param : g_h1;
    float* hout = first ? g_h1 : g_h2;

    int tid = threadIdx.x;
    int lane = tid & 31;
    int wid = tid >> 5;
    int wm = wid >> 2;       // 0..1 -> m offset wm*64
    int wn = wid & 3;        // 0..3 -> n offset wn*32

    if (tid < 128) sbias[tid] = b[tid];

    // convert weights once: [o][k] hi/lo bf16, padded rows
    for (int i = 0; i < 64; i++) {
        int p = tid + i * 256;          // 0..16383
        int o = p >> 7;
        int kp = p & 127;               // k-pair index, k = kp*2
        float2 v = (kp < 64) ? *(const float2*)(Wl + o * 128 + kp * 2)
                             : *(const float2*)(Wr + o * 128 + (kp - 64) * 2);
        uint32_t hi, lo;
        cvt_pair(v.x, v.y, hi, lo);
        *(uint32_t*)(smem + B_HI_OFF + o * RSB + kp * 4) = hi;
        *(uint32_t*)(smem + B_LO_OFF + o * RSB + kp * 4) = lo;
    }
    __syncthreads();

    // per-lane ldmatrix address components
    int sub = lane >> 3;                 // 0..3
    int rin = lane & 7;
    // A: matrices {rows0-7,k0}, {rows8-15,k0}, {rows0-7,k8}, {rows8-15,k8}
    int a_row = (sub & 1) * 8 + rin;
    int a_kof = (sub >> 1) * 8;
    // B: matrices {n0-7,k0}, {n0-7,k8}, {n8-15,k0}, {n8-15,k8}
    int b_row = (sub >> 1) * 8 + rin;
    int b_kof = (sub & 1) * 8;

    for (int t = 0; t < TILES_PER_BLK; t++) {
        int node0 = (blockIdx.x * TILES_PER_BLK + t) * 128;
        if (node0 >= NN) break;

        float acc[4][4][4];
#pragma unroll
        for (int mt = 0; mt < 4; mt++)
#pragma unroll
            for (int nt = 0; nt < 4; nt++)
#pragma unroll
                for (int j = 0; j < 4; j++) acc[mt][nt][j] = 0.f;

        for (int half = 0; half < 2; half++) {
            // convert A half: 128 rows x 128 k
            const float* Asrc = half ? xin : g_agg;
            for (int i = 0; i < 32; i++) {
                int p = tid + i * 256;       // 0..8191
                int r = p >> 6;
                int kp = p & 63;             // k = kp*2 (0..126)
                int node = node0 + r;
                float2 v = make_float2(0.f, 0.f);
                if (node < NN) v = *(const float2*)(Asrc + (size_t)node * D + kp * 2);
                uint32_t hi, lo;
                cvt_pair(v.x, v.y, hi, lo);
                *(uint32_t*)(smem + A_HI_OFF + r * RSA + kp * 4) = hi;
                *(uint32_t*)(smem + A_LO_OFF + r * RSA + kp * 4) = lo;
            }
            __syncthreads();

#pragma unroll
            for (int ks = 0; ks < 8; ks++) {
                int akc = ks * 16 + a_kof;        // k within half (bf16 idx)
                int bkc = half * 128 + ks * 16 + b_kof;

                uint32_t ah[4][4], al[4][4];
#pragma unroll
                for (int mt = 0; mt < 4; mt++) {
                    uint32_t ro = (uint32_t)((wm * 64 + mt * 16 + a_row) * RSA + akc * 2);
                    ldm_x4(sbase + A_HI_OFF + ro, ah[mt]);
                    ldm_x4(sbase + A_LO_OFF + ro, al[mt]);
                }
                uint32_t bh[2][4], bl[2][4];
#pragma unroll
                for (int np = 0; np < 2; np++) {
                    uint32_t ro = (uint32_t)((wn * 32 + np * 16 + b_row) * RSB + bkc * 2);
                    ldm_x4(sbase + B_HI_OFF + ro, bh[np]);
                    ldm_x4(sbase + B_LO_OFF + ro, bl[np]);
                }
#pragma unroll
                for (int mt = 0; mt < 4; mt++) {
#pragma unroll
                    for (int nt = 0; nt < 4; nt++) {
                        const uint32_t* Bh = &bh[nt >> 1][(nt & 1) * 2];
                        const uint32_t* Bl = &bl[nt >> 1][(nt & 1) * 2];
                        mma_bf16(acc[mt][nt], ah[mt], Bh);   // hh
                        mma_bf16(acc[mt][nt], ah[mt], Bl);   // hl
                        mma_bf16(acc[mt][nt], al[mt], Bh);   // lh
                    }
                }
            }
            __syncthreads();
        }

        // epilogue: bias + relu, store fp32
        int qr = lane >> 2;              // 0..7
        int qc = (lane & 3) * 2;         // 0,2,4,6
#pragma unroll
        for (int mt = 0; mt < 4; mt++) {
            int n0 = node0 + wm * 64 + mt * 16 + qr;
            int n1 = n0 + 8;
#pragma unroll
            for (int nt = 0; nt < 4; nt++) {
                int o = wn * 32 + nt * 8 + qc;
                float b0 = sbias[o], b1 = sbias[o + 1];
                if (n0 < NN) {
                    float2 v;
                    v.x = fmaxf(acc[mt][nt][0] + b0, 0.f);
                    v.y = fmaxf(acc[mt][nt][1] + b1, 0.f);
                    *(float2*)(hout + (size_t)n0 * D + o) = v;
                }
                if (n1 < NN) {
                    float2 v;
                    v.x = fmaxf(acc[mt][nt][2] + b0, 0.f);
                    v.y = fmaxf(acc[mt][nt][3] + b1, 0.f);
                    *(float2*)(hout + (size_t)n1 * D + o) = v;
                }
            }
        }
        __syncthreads();
    }
}

// ---------------------------------------------------------------------------
// final: logits = [h1|h2] @ W_lin^T + b_lin ; log_softmax. 1 thread per node.
__global__ void __launch_bounds__(128) k_final(const float* __restrict__ Wlin,
                                               const float* __restrict__ blin,
                                               float* __restrict__ out) {
    __shared__ __align__(16) float sWt[256 * DOUT];
    __shared__ float sb[DOUT];
    int tid = threadIdx.x;
    for (int i = tid; i < 256 * DOUT; i += 128) {
        int o = i >> 8;
        int k = i & 255;
        sWt[k * DOUT + o] = Wlin[o * 256 + k];
    }
    if (tid < DOUT) sb[tid] = blin[tid];
    __syncthreads();

    int node = blockIdx.x * 128 + tid;
    if (node >= NN) return;

    float acc[DOUT];
#pragma unroll
    for (int o = 0; o < DOUT; o++) acc[o] = sb[o];

    const float* h1p = g_h1 + (size_t)node * D;
    const float* h2p = g_h2 + (size_t)node * D;
#pragma unroll
    for (int half = 0; half < 2; half++) {
        const float* hp = half ? h2p : h1p;
        for (int k4 = 0; k4 < 128; k4 += 4) {
            float4 a = *(const float4*)(hp + k4);
            float av[4] = {a.x, a.y, a.z, a.w};
#pragma unroll
            for (int kkk = 0; kkk < 4; kkk++) {
                const float* wr = sWt + (half * 128 + k4 + kkk) * DOUT;
                float v = av[kkk];
#pragma unroll
                for (int o4 = 0; o4 < DOUT; o4 += 4) {
                    float4 w = *(const float4*)(wr + o4);
                    acc[o4 + 0] += v * w.x;
                    acc[o4 + 1] += v * w.y;
                    acc[o4 + 2] += v * w.z;
                    acc[o4 + 3] += v * w.w;
                }
            }
        }
    }

    float m = acc[0];
#pragma unroll
    for (int o = 1; o < DOUT; o++) m = fmaxf(m, acc[o]);
    float s = 0.f;
#pragma unroll
    for (int o = 0; o < DOUT; o++) s += expf(acc[o] - m);
    float lse = m + logf(s);
    float* op = out + (size_t)node * DOUT;
#pragma unroll
    for (int o = 0; o < DOUT; o++) op[o] = acc[o] - lse;
}

// ---------------------------------------------------------------------------
extern "C" void kernel_launch(void* const* d_in, const int* in_sizes, int n_in,
                              void* d_out, int out_size) {
    const float* x    = (const float*)d_in[0];
    const void*  ei   = d_in[1];
    const float* W1l  = (const float*)d_in[2];
    const float* b1   = (const float*)d_in[3];
    const float* W1r  = (const float*)d_in[4];
    const float* W2l  = (const float*)d_in[5];
    const float* b2   = (const float*)d_in[6];
    const float* W2r  = (const float*)d_in[7];
    const float* Wlin = (const float*)d_in[8];
    const float* blin = (const float*)d_in[9];
    float*       out  = (float*)d_out;

    cudaFuncSetAttribute(k_layer_mma, cudaFuncAttributeMaxDynamicSharedMemorySize,
                         SMEM_MMA_BYTES);

    const int edge_blocks  = (NE + 255) / 256;      // 3125
    const int agg_blocks   = (NN * 32 + 255) / 256; // 6250
    const int final_blocks = (NN + 127) / 128;      // 391

    // CSR build (once, reused by both layers)
    k_detect<<<1, 256>>>((const int*)ei);
    k_zero_cnt<<<NBLK, 256>>>();
    k_hist<<<edge_blocks, 256>>>(ei);
    k_scanA<<<NBLK, 256>>>();
    k_scanB<<<1, 256>>>();
    k_scanC<<<NBLK, 256>>>();
    k_fill<<<edge_blocks, 256>>>(ei);

    // layer 1
    k_agg<<<agg_blocks, 256>>>(x, 0);
    k_layer_mma<<<MMA_GRID, 256, SMEM_MMA_BYTES>>>(x, W1l, W1r, b1, 1);

    // layer 2
    k_agg<<<agg_blocks, 256>>>(nullptr, 1);
    k_layer_mma<<<MMA_GRID, 256, SMEM_MMA_BYTES>>>(nullptr, W2l, W2r, b2, 0);

    // head
    k_final<<<final_blocks, 128>>>(Wlin, blin, out);
}

// round 6
// speedup vs baseline: 1.6469x; 1.1426x over previous
#include <cuda_runtime.h>
#include <cuda_bf16.h>
#include <math.h>
#include <stdint.h>

#define NN   50000
#define NE   800000
#define D    128
#define DOUT 40
#define NBLK ((NN + 255) / 256)   // 196

// scratch (allocation-free rule: __device__ globals)
__device__ float g_agg[NN * D];
__device__ float g_h1[NN * D];
__device__ float g_h2[NN * D];
__device__ float g_dinv[NN];
__device__ int   g_cnt[NN];
__device__ int   g_rowptr[NN];
__device__ int   g_cursor[NN];
__device__ int   g_bsum[256];
__device__ int   g_csr[NE];
__device__ int   g_is64;

// ---------------------------------------------------------------------------
// init: zero counts; block 0 also detects edge_index dtype (int32 vs int64)
__global__ void k_init(const int* __restrict__ ei32) {
    int i = blockIdx.x * 256 + threadIdx.x;
    if (i < NN) g_cnt[i] = 0;
    if (blockIdx.x == 0) {
        int nz = (ei32[2 * threadIdx.x + 1] != 0) ? 1 : 0;
        int cnt_nz = __syncthreads_count(nz);
        if (threadIdx.x == 0) g_is64 = (cnt_nz == 0) ? 1 : 0;
    }
}

__device__ __forceinline__ int edge_val(const void* ei, long long idx, int is64) {
    if (is64) return (int)((const long long*)ei)[idx];
    return ((const int*)ei)[idx];
}

__global__ void __launch_bounds__(256) k_hist(const void* __restrict__ ei) {
    int e = blockIdx.x * blockDim.x + threadIdx.x;
    if (e >= NE) return;
    int is64 = g_is64;
    int d = edge_val(ei, (long long)NE + e, is64);
    atomicAdd(&g_cnt[d], 1);
}

__global__ void __launch_bounds__(256) k_scanA() {
    __shared__ int sb[256];
    int t = threadIdx.x;
    int i = blockIdx.x * 256 + t;
    int v = (i < NN) ? g_cnt[i] : 0;
    sb[t] = v;
    __syncthreads();
    for (int off = 1; off < 256; off <<= 1) {
        int tv = (t >= off) ? sb[t - off] : 0;
        __syncthreads();
        sb[t] += tv;
        __syncthreads();
    }
    int incl = sb[t];
    if (i < NN) g_rowptr[i] = incl - v;
    if (t == 255) g_bsum[blockIdx.x] = incl;
}

__global__ void __launch_bounds__(256) k_scanB() {
    __shared__ int sb[256];
    int t = threadIdx.x;
    int v = (t < NBLK) ? g_bsum[t] : 0;
    sb[t] = v;
    __syncthreads();
    for (int off = 1; off < 256; off <<= 1) {
        int tv = (t >= off) ? sb[t - off] : 0;
        __syncthreads();
        sb[t] += tv;
        __syncthreads();
    }
    if (t < NBLK) g_bsum[t] = sb[t] - v;
}

__global__ void __launch_bounds__(256) k_scanC() {
    int i = blockIdx.x * 256 + threadIdx.x;
    if (i < NN) {
        int rp = g_rowptr[i] + g_bsum[blockIdx.x];
        g_rowptr[i] = rp;
        g_cursor[i] = rp;
        g_dinv[i] = 1.0f / (float)max(g_cnt[i], 1);
    }
}

__global__ void __launch_bounds__(256) k_fill(const void* __restrict__ ei) {
    int e = blockIdx.x * blockDim.x + threadIdx.x;
    if (e >= NE) return;
    int is64 = g_is64;
    int s = edge_val(ei, e, is64);
    int d = edge_val(ei, (long long)NE + e, is64);
    int pos = atomicAdd(&g_cursor[d], 1);
    g_csr[pos] = s;
}

// ---------------------------------------------------------------------------
// gather-aggregate (mean): one warp per node, 4-way unrolled
__global__ void __launch_bounds__(256) k_agg(const float* __restrict__ feat_param,
                                             int use_h1) {
    int t = blockIdx.x * blockDim.x + threadIdx.x;
    int node = t >> 5;
    if (node >= NN) return;
    int lane = t & 31;
    const float* feat = use_h1 ? g_h1 : feat_param;

    int start = g_rowptr[node];
    int end = start + g_cnt[node];

    float4 a0 = make_float4(0.f, 0.f, 0.f, 0.f);
    float4 a1 = make_float4(0.f, 0.f, 0.f, 0.f);
    float4 a2 = make_float4(0.f, 0.f, 0.f, 0.f);
    float4 a3 = make_float4(0.f, 0.f, 0.f, 0.f);

    int e = start;
    for (; e + 3 < end; e += 4) {
        int s0 = g_csr[e];
        int s1 = g_csr[e + 1];
        int s2 = g_csr[e + 2];
        int s3 = g_csr[e + 3];
        float4 v0 = *((const float4*)(feat + (size_t)s0 * D) + lane);
        float4 v1 = *((const float4*)(feat + (size_t)s1 * D) + lane);
        float4 v2 = *((const float4*)(feat + (size_t)s2 * D) + lane);
        float4 v3 = *((const float4*)(feat + (size_t)s3 * D) + lane);
        a0.x += v0.x; a0.y += v0.y; a0.z += v0.z; a0.w += v0.w;
        a1.x += v1.x; a1.y += v1.y; a1.z += v1.z; a1.w += v1.w;
        a2.x += v2.x; a2.y += v2.y; a2.z += v2.z; a2.w += v2.w;
        a3.x += v3.x; a3.y += v3.y; a3.z += v3.z; a3.w += v3.w;
    }
    for (; e < end; e++) {
        int s0 = g_csr[e];
        float4 v0 = *((const float4*)(feat + (size_t)s0 * D) + lane);
        a0.x += v0.x; a0.y += v0.y; a0.z += v0.z; a0.w += v0.w;
    }

    float di = g_dinv[node];
    float4 r;
    r.x = (a0.x + a1.x + a2.x + a3.x) * di;
    r.y = (a0.y + a1.y + a2.y + a3.y) * di;
    r.z = (a0.z + a1.z + a2.z + a3.z) * di;
    r.w = (a0.w + a1.w + a2.w + a3.w) * di;
    *((float4*)(g_agg + (size_t)node * D) + lane) = r;
}

// ---------------------------------------------------------------------------
// common MMA helpers
__device__ __forceinline__ uint32_t smem_u32(const void* p) {
    uint32_t a;
    asm("{ .reg .u64 t; cvta.to.shared.u64 t, %1; cvt.u32.u64 %0, t; }"
        : "=r"(a) : "l"(p));
    return a;
}

__device__ __forceinline__ void ldm_x4(uint32_t addr, uint32_t* r) {
    asm volatile("ldmatrix.sync.aligned.m8n8.x4.shared.b16 {%0,%1,%2,%3}, [%4];"
                 : "=r"(r[0]), "=r"(r[1]), "=r"(r[2]), "=r"(r[3]) : "r"(addr));
}

__device__ __forceinline__ void mma_bf16(float* d, const uint32_t* a,
                                         const uint32_t* b) {
    asm volatile(
        "mma.sync.aligned.m16n8k16.row.col.f32.bf16.bf16.f32 "
        "{%0,%1,%2,%3}, {%4,%5,%6,%7}, {%8,%9}, {%0,%1,%2,%3};"
        : "+f"(d[0]), "+f"(d[1]), "+f"(d[2]), "+f"(d[3])
        : "r"(a[0]), "r"(a[1]), "r"(a[2]), "r"(a[3]), "r"(b[0]), "r"(b[1]));
}

__device__ __forceinline__ void cvt_pair(float x0, float x1, uint32_t& hi,
                                         uint32_t& lo) {
    __nv_bfloat16 h0 = __float2bfloat16(x0);
    __nv_bfloat16 h1 = __float2bfloat16(x1);
    float r0 = x0 - __bfloat162float(h0);
    float r1 = x1 - __bfloat162float(h1);
    __nv_bfloat162 hp(h0, h1);
    __nv_bfloat162 lp(__float2bfloat16(r0), __float2bfloat16(r1));
    hi = *reinterpret_cast<uint32_t*>(&hp);
    lo = *reinterpret_cast<uint32_t*>(&lp);
}

// ---------------------------------------------------------------------------
// mma.sync bf16 layer with hi/lo split (3 passes: hh + hl + lh). 512 threads.
// Per 128-node tile: D[128,128] = A[128,256] @ W[128,256]^T, fp32 accum.
#define TILES_PER_BLK 3
#define NTILES ((NN + 127) / 128)                               // 391
#define MMA_GRID ((NTILES + TILES_PER_BLK - 1) / TILES_PER_BLK) // 131

#define SB_OFF   0
#define A_HI_OFF 1024
#define A_LO_OFF (A_HI_OFF + 34816)       // 128 rows * 272B
#define B_HI_OFF (A_LO_OFF + 34816)       // 70656
#define B_LO_OFF (B_HI_OFF + 67584)       // 128 rows * 528B
#define SMEM_MMA_BYTES (B_LO_OFF + 67584) // 205824
#define RSA 272
#define RSB 528

__global__ void __launch_bounds__(512, 1) k_layer_mma(const float* __restrict__ xin_param,
                                                      const float* __restrict__ Wl,
                                                      const float* __restrict__ Wr,
                                                      const float* __restrict__ b,
                                                      int first) {
    extern __shared__ char smem[];
    uint32_t sbase = smem_u32(smem);
    float* sbias = (float*)(smem + SB_OFF);

    const float* xin = first ? xin_param : g_h1;
    float* hout = first ? g_h1 : g_h2;

    int tid = threadIdx.x;
    int lane = tid & 31;
    int wid = tid >> 5;
    int wm = wid >> 2;       // 0..3 -> m offset wm*32
    int wn = wid & 3;        // 0..3 -> n offset wn*32

    if (tid < 128) sbias[tid] = b[tid];

    // convert weights once: [o][k] hi/lo bf16, padded rows
    for (int i = 0; i < 32; i++) {
        int p = tid + i * 512;          // 0..16383
        int o = p >> 7;
        int kp = p & 127;
        float2 v = (kp < 64) ? *(const float2*)(Wl + o * 128 + kp * 2)
                             : *(const float2*)(Wr + o * 128 + (kp - 64) * 2);
        uint32_t hi, lo;
        cvt_pair(v.x, v.y, hi, lo);
        *(uint32_t*)(smem + B_HI_OFF + o * RSB + kp * 4) = hi;
        *(uint32_t*)(smem + B_LO_OFF + o * RSB + kp * 4) = lo;
    }
    __syncthreads();

    int sub = lane >> 3;
    int rin = lane & 7;
    int a_row = (sub & 1) * 8 + rin;
    int a_kof = (sub >> 1) * 8;
    int b_row = (sub >> 1) * 8 + rin;
    int b_kof = (sub & 1) * 8;

    for (int t = 0; t < TILES_PER_BLK; t++) {
        int node0 = (blockIdx.x * TILES_PER_BLK + t) * 128;
        if (node0 >= NN) break;

        float acc[2][4][4];
#pragma unroll
        for (int mt = 0; mt < 2; mt++)
#pragma unroll
            for (int nt = 0; nt < 4; nt++)
#pragma unroll
                for (int j = 0; j < 4; j++) acc[mt][nt][j] = 0.f;

        for (int half = 0; half < 2; half++) {
            const float* Asrc = half ? xin : g_agg;
            for (int i = 0; i < 16; i++) {
                int p = tid + i * 512;       // 0..8191
                int r = p >> 6;
                int kp = p & 63;
                int node = node0 + r;
                float2 v = make_float2(0.f, 0.f);
                if (node < NN) v = *(const float2*)(Asrc + (size_t)node * D + kp * 2);
                uint32_t hi, lo;
                cvt_pair(v.x, v.y, hi, lo);
                *(uint32_t*)(smem + A_HI_OFF + r * RSA + kp * 4) = hi;
                *(uint32_t*)(smem + A_LO_OFF + r * RSA + kp * 4) = lo;
            }
            __syncthreads();

#pragma unroll
            for (int ks = 0; ks < 8; ks++) {
                int akc = ks * 16 + a_kof;
                int bkc = half * 128 + ks * 16 + b_kof;

                uint32_t ah[2][4], al[2][4];
#pragma unroll
                for (int mt = 0; mt < 2; mt++) {
                    uint32_t ro = (uint32_t)((wm * 32 + mt * 16 + a_row) * RSA + akc * 2);
                    ldm_x4(sbase + A_HI_OFF + ro, ah[mt]);
                    ldm_x4(sbase + A_LO_OFF + ro, al[mt]);
                }
                uint32_t bh[2][4], bl[2][4];
#pragma unroll
                for (int np = 0; np < 2; np++) {
                    uint32_t ro = (uint32_t)((wn * 32 + np * 16 + b_row) * RSB + bkc * 2);
                    ldm_x4(sbase + B_HI_OFF + ro, bh[np]);
                    ldm_x4(sbase + B_LO_OFF + ro, bl[np]);
                }
#pragma unroll
                for (int mt = 0; mt < 2; mt++) {
#pragma unroll
                    for (int nt = 0; nt < 4; nt++) {
                        const uint32_t* Bh = &bh[nt >> 1][(nt & 1) * 2];
                        const uint32_t* Bl = &bl[nt >> 1][(nt & 1) * 2];
                        mma_bf16(acc[mt][nt], ah[mt], Bh);
                        mma_bf16(acc[mt][nt], ah[mt], Bl);
                        mma_bf16(acc[mt][nt], al[mt], Bh);
                    }
                }
            }
            __syncthreads();
        }

        int qr = lane >> 2;
        int qc = (lane & 3) * 2;
#pragma unroll
        for (int mt = 0; mt < 2; mt++) {
            int n0 = node0 + wm * 32 + mt * 16 + qr;
            int n1 = n0 + 8;
#pragma unroll
            for (int nt = 0; nt < 4; nt++) {
                int o = wn * 32 + nt * 8 + qc;
                float b0 = sbias[o], b1 = sbias[o + 1];
                if (n0 < NN) {
                    float2 v;
                    v.x = fmaxf(acc[mt][nt][0] + b0, 0.f);
                    v.y = fmaxf(acc[mt][nt][1] + b1, 0.f);
                    *(float2*)(hout + (size_t)n0 * D + o) = v;
                }
                if (n1 < NN) {
                    float2 v;
                    v.x = fmaxf(acc[mt][nt][2] + b0, 0.f);
                    v.y = fmaxf(acc[mt][nt][3] + b1, 0.f);
                    *(float2*)(hout + (size_t)n1 * D + o) = v;
                }
            }
        }
        __syncthreads();
    }
}

// ---------------------------------------------------------------------------
// final head on MMA: logits = [h1|h2] @ W_lin^T + b_lin ; log_softmax in regs.
// 256 threads / 8 warps, one 128-node tile per block, K=256, N padded to 48.
#define RSF 528
#define FA_HI 1024
#define FA_LO (FA_HI + 128 * RSF)            // 68608
#define FB_HI (FA_LO + 128 * RSF)            // 136192
#define FB_LO (FB_HI + 48 * RSF)             // 161536
#define SMEM_FIN_BYTES (FB_LO + 48 * RSF)    // 186880

__global__ void __launch_bounds__(256, 1) k_final_mma(const float* __restrict__ Wlin,
                                                      const float* __restrict__ blin,
                                                      float* __restrict__ out) {
    extern __shared__ char smem[];
    uint32_t sbase = smem_u32(smem);
    float* sbias = (float*)(smem + SB_OFF);

    int tid = threadIdx.x;
    int lane = tid & 31;
    int wid = tid >> 5;
    int node0 = blockIdx.x * 128;

    if (tid < 48) sbias[tid] = (tid < DOUT) ? blin[tid] : 0.f;

    // convert Wlin [40][256] -> padded 48 rows hi/lo
    for (int i = 0; i < 24; i++) {
        int p = tid + i * 256;          // 0..6143
        int o = p >> 7;
        int kp = p & 127;
        float2 v = make_float2(0.f, 0.f);
        if (o < DOUT) v = *(const float2*)(Wlin + o * 256 + kp * 2);
        uint32_t hi, lo;
        cvt_pair(v.x, v.y, hi, lo);
        *(uint32_t*)(smem + FB_HI + o * RSF + kp * 4) = hi;
        *(uint32_t*)(smem + FB_LO + o * RSF + kp * 4) = lo;
    }

    // convert A = [h1 | h2] tile: 128 rows x 256 k
    for (int i = 0; i < 64; i++) {
        int p = tid + i * 256;          // 0..16383
        int r = p >> 7;
        int kp = p & 127;
        int node = node0 + r;
        float2 v = make_float2(0.f, 0.f);
        if (node < NN) {
            const float* src = (kp < 64) ? (g_h1 + (size_t)node * D + kp * 2)
                                         : (g_h2 + (size_t)node * D + (kp - 64) * 2);
            v = *(const float2*)src;
        }
        uint32_t hi, lo;
        cvt_pair(v.x, v.y, hi, lo);
        *(uint32_t*)(smem + FA_HI + r * RSF + kp * 4) = hi;
        *(uint32_t*)(smem + FA_LO + r * RSF + kp * 4) = lo;
    }
    __syncthreads();

    int sub = lane >> 3;
    int rin = lane & 7;
    int a_row = (sub & 1) * 8 + rin;
    int a_kof = (sub >> 1) * 8;
    int b_row = (sub >> 1) * 8 + rin;
    int b_kof = (sub & 1) * 8;

    float acc[5][4];
#pragma unroll
    for (int nt = 0; nt < 5; nt++)
#pragma unroll
        for (int j = 0; j < 4; j++) acc[nt][j] = 0.f;

#pragma unroll
    for (int ks = 0; ks < 16; ks++) {
        uint32_t ah[4], al[4];
        {
            uint32_t ro = (uint32_t)((wid * 16 + a_row) * RSF + (ks * 16 + a_kof) * 2);
            ldm_x4(sbase + FA_HI + ro, ah);
            ldm_x4(sbase + FA_LO + ro, al);
        }
        uint32_t bh[3][4], bl[3][4];
#pragma unroll
        for (int np = 0; np < 3; np++) {
            uint32_t ro = (uint32_t)((np * 16 + b_row) * RSF + (ks * 16 + b_kof) * 2);
            ldm_x4(sbase + FB_HI + ro, bh[np]);
            ldm_x4(sbase + FB_LO + ro, bl[np]);
        }
#pragma unroll
        for (int nt = 0; nt < 5; nt++) {
            const uint32_t* Bh = &bh[nt >> 1][(nt & 1) * 2];
            const uint32_t* Bl = &bl[nt >> 1][(nt & 1) * 2];
            mma_bf16(acc[nt], ah, Bh);
            mma_bf16(acc[nt], ah, Bl);
            mma_bf16(acc[nt], al, Bh);
        }
    }

    // bias
    int qc = (lane & 3) * 2;
#pragma unroll
    for (int nt = 0; nt < 5; nt++) {
        int o = nt * 8 + qc;
        acc[nt][0] += sbias[o];
        acc[nt][1] += sbias[o + 1];
        acc[nt][2] += sbias[o];
        acc[nt][3] += sbias[o + 1];
    }

    // log_softmax over 40 cols, rows r0 (regs 0,1) and r1 (regs 2,3)
    float m0 = -1e30f, m1 = -1e30f;
#pragma unroll
    for (int nt = 0; nt < 5; nt++) {
        m0 = fmaxf(m0, fmaxf(acc[nt][0], acc[nt][1]));
        m1 = fmaxf(m1, fmaxf(acc[nt][2], acc[nt][3]));
    }
#pragma unroll
    for (int d = 1; d <= 2; d <<= 1) {
        m0 = fmaxf(m0, __shfl_xor_sync(0xffffffffu, m0, d));
        m1 = fmaxf(m1, __shfl_xor_sync(0xffffffffu, m1, d));
    }
    float s0 = 0.f, s1 = 0.f;
#pragma unroll
    for (int nt = 0; nt < 5; nt++) {
        s0 += expf(acc[nt][0] - m0) + expf(acc[nt][1] - m0);
        s1 += expf(acc[nt][2] - m1) + expf(acc[nt][3] - m1);
    }
#pragma unroll
    for (int d = 1; d <= 2; d <<= 1) {
        s0 += __shfl_xor_sync(0xffffffffu, s0, d);
        s1 += __shfl_xor_sync(0xffffffffu, s1, d);
    }
    float lse0 = m0 + logf(s0);
    float lse1 = m1 + logf(s1);

    int qr = lane >> 2;
    int r0 = node0 + wid * 16 + qr;
    int r1 = r0 + 8;
#pragma unroll
    for (int nt = 0; nt < 5; nt++) {
        int o = nt * 8 + qc;
        if (r0 < NN) {
            float2 v = make_float2(acc[nt][0] - lse0, acc[nt][1] - lse0);
            *(float2*)(out + (size_t)r0 * DOUT + o) = v;
        }
        if (r1 < NN) {
            float2 v = make_float2(acc[nt][2] - lse1, acc[nt][3] - lse1);
            *(float2*)(out + (size_t)r1 * DOUT + o) = v;
        }
    }
}

// ---------------------------------------------------------------------------
extern "C" void kernel_launch(void* const* d_in, const int* in_sizes, int n_in,
                              void* d_out, int out_size) {
    const float* x    = (const float*)d_in[0];
    const void*  ei   = d_in[1];
    const float* W1l  = (const float*)d_in[2];
    const float* b1   = (const float*)d_in[3];
    const float* W1r  = (const float*)d_in[4];
    const float* W2l  = (const float*)d_in[5];
    const float* b2   = (const float*)d_in[6];
    const float* W2r  = (const float*)d_in[7];
    const float* Wlin = (const float*)d_in[8];
    const float* blin = (const float*)d_in[9];
    float*       out  = (float*)d_out;

    cudaFuncSetAttribute(k_layer_mma, cudaFuncAttributeMaxDynamicSharedMemorySize,
                         SMEM_MMA_BYTES);
    cudaFuncSetAttribute(k_final_mma, cudaFuncAttributeMaxDynamicSharedMemorySize,
                         SMEM_FIN_BYTES);

    const int edge_blocks  = (NE + 255) / 256;      // 3125
    const int agg_blocks   = (NN * 32 + 255) / 256; // 6250

    // CSR build (once, reused by both layers)
    k_init<<<NBLK, 256>>>((const int*)ei);
    k_hist<<<edge_blocks, 256>>>(ei);
    k_scanA<<<NBLK, 256>>>();
    k_scanB<<<1, 256>>>();
    k_scanC<<<NBLK, 256>>>();
    k_fill<<<edge_blocks, 256>>>(ei);

    // layer 1
    k_agg<<<agg_blocks, 256>>>(x, 0);
    k_layer_mma<<<MMA_GRID, 512, SMEM_MMA_BYTES>>>(x, W1l, W1r, b1, 1);

    // layer 2
    k_agg<<<agg_blocks, 256>>>(nullptr, 1);
    k_layer_mma<<<MMA_GRID, 512, SMEM_MMA_BYTES>>>(nullptr, W2l, W2r, b2, 0);

    // head
    k_final_mma<<<NTILES, 256, SMEM_FIN_BYTES>>>(Wlin, blin, out);
}